// round 14
// baseline (speedup 1.0000x reference)
#include <cuda_runtime.h>
#include <cuda_bf16.h>
#include <math.h>
#include <stdint.h>

#define Ln 128
#define Bn 4096
#define Dn 300
#define XROW 336                // 320 int8 + 16B pad (21*16B, odd granules -> conflict-free)
#define SM_X   0
#define SM_AL  43008            // 128*336 : per-row alpha (128 floats)
#define SM_RA  43520
#define SM_RC  44544
#define DYN_SMEM 45568

// Fragment-ordered int8 B image: blob (ch,ks,wn) of [lane][20 u32] (ch1 uses 18 + 2 pad).
// blob = ch*20 + ks*2 + wn, ks=0..9 (k32 steps). u32 (s,reg): 4 int8, byte j = Wq[k0+j][n],
// n = colBase + 8s + g, k0 = 32ks + 16reg + 4q.  per-ks stride = 1280 u32 (5120B).
#define NBLOB (2*10*2)
__device__ __align__(16) uint32_t g_Wfrag[NBLOB * 32 * 20];
__device__ unsigned g_amaxBits;
__device__ float g_A[Ln * Bn];
__device__ float g_C[Ln * Bn];

__device__ __forceinline__ uint32_t smem_to_u32(const void* p) {
    uint32_t a;
    asm("{ .reg .u64 t; cvta.to.shared.u64 t, %1; cvt.u32.u64 %0, t; }" : "=r"(a) : "l"(p));
    return a;
}

#define LDSM_X4(r, addr)                                                        \
    asm volatile("ldmatrix.sync.aligned.m8n8.x4.shared.b16 {%0,%1,%2,%3}, [%4];"\
        : "=r"((r)[0]),"=r"((r)[1]),"=r"((r)[2]),"=r"((r)[3]) : "r"(addr))
#define MMAS8(d, a, b0, b1)                                                     \
    asm volatile("mma.sync.aligned.m16n8k32.row.col.s32.s8.s8.s32 "             \
        "{%0,%1,%2,%3}, {%4,%5,%6,%7}, {%8,%9}, {%0,%1,%2,%3};"                 \
        : "+r"((d)[0]),"+r"((d)[1]),"+r"((d)[2]),"+r"((d)[3])                   \
        : "r"((a)[0]),"r"((a)[1]),"r"((a)[2]),"r"((a)[3]), "r"(b0),"r"(b1))

// ============ kernel 0a: zero amax ============
__global__ void zeroAmax_kernel() { g_amaxBits = 0u; }

// ============ kernel 0b: amax of Ws = W + W^T ============
__global__ void amax_kernel(const float* __restrict__ W) {
    int idx = blockIdx.x * 256 + threadIdx.x;
    if (idx >= Dn * Dn) return;
    int i = idx / Dn, j = idx % Dn;
    float v = fabsf(W[i * Dn + j] + W[j * Dn + i]);
    atomicMax(&g_amaxBits, __float_as_uint(v));
}

// ============ kernel 1: build fragment-ordered int8 Ws image ============
__global__ void prepW_kernel(const float* __restrict__ W) {
    int idx = blockIdx.x * 256 + threadIdx.x;
    if (idx >= NBLOB * 32 * 20) return;
    int su   = idx % 20;
    int lane = (idx / 20) & 31;
    int blob = idx / (32 * 20);
    int wn = blob & 1, ks = (blob >> 1) % 10, ch = blob / 20;
    int g = lane >> 2, q = lane & 3;
    uint32_t pk = 0u;
    const int nsu = ch ? 18 : 20;
    if (su < nsu) {
        int s = su >> 1, reg = su & 1;
        int n  = ch ? (160 + wn * 72 + 8 * s + g) : (wn * 80 + 8 * s + g);
        int k0 = 32 * ks + 16 * reg + 4 * q;
        float invb = 127.0f / __uint_as_float(g_amaxBits);
        uint32_t r = 0;
        if (n < Dn) {
            #pragma unroll
            for (int j = 0; j < 4; j++) {
                int k = k0 + j;
                int b = 0;
                if (k < Dn) {
                    float v = (W[k * Dn + n] + W[n * Dn + k]) * invb;
                    b = __float2int_rn(v);
                }
                r |= ((uint32_t)(b & 255)) << (8 * j);
            }
        }
        pk = r;
    }
    g_Wfrag[idx] = pk;
}

// ---------------- templated chunk body (k-loop + dot epilogue) ----------------
template <int NS>
__device__ __forceinline__ void run_chunk(
    const char* smemc, uint32_t aBase0, uint32_t aBase1,
    const uint32_t* bp, int colBase,
    const float* __restrict__ S, size_t m0, bool hasPrev,
    int r0, int g, int q, float (&aA)[2][2], float (&cA)[2][2])
{
    int acc[2][NS][4];
    #pragma unroll
    for (int t = 0; t < 2; t++)
        #pragma unroll
        for (int s = 0; s < NS; s++)
            #pragma unroll
            for (int i = 0; i < 4; i++) acc[t][s][i] = 0;

    #pragma unroll 1
    for (int ks = 0; ks < 10; ks++) {
        uint32_t a0[4], a1[4];
        LDSM_X4(a0, aBase0 + ks * 32);
        LDSM_X4(a1, aBase1 + ks * 32);
        uint32_t bw[2 * NS];
        #pragma unroll
        for (int j = 0; j < NS / 2; j++) {
            uint4 v = __ldg((const uint4*)bp + j);
            bw[4 * j] = v.x; bw[4 * j + 1] = v.y; bw[4 * j + 2] = v.z; bw[4 * j + 3] = v.w;
        }
        if constexpr (NS & 1) {
            uint2 v = __ldg((const uint2*)(bp + 4 * (NS / 2)));
            bw[2 * NS - 2] = v.x; bw[2 * NS - 1] = v.y;
        }
        bp += 2 * 32 * 20;               // next ks (stride 5120B)
        #pragma unroll
        for (int s = 0; s < NS; s++) {
            MMAS8(acc[0][s], a0, bw[2 * s], bw[2 * s + 1]);
            MMAS8(acc[1][s], a1, bw[2 * s], bw[2 * s + 1]);
        }
    }

    // dot epilogue: quantized self row from X smem (bytes), prev row fp32 from gmem
    const int lo = (q & 1) * 2;          // first byte index within the aligned word
    #pragma unroll
    for (int t = 0; t < 2; t++) {
        const int rowA = r0 + 16 * t + g;
        const int rowB = rowA + 8;
        const float* pA = S + (m0 + rowA - (size_t)Bn) * Dn;
        const float* pB = S + (m0 + rowB - (size_t)Bn) * Dn;
        #pragma unroll
        for (int s = 0; s < NS; s++) {
            const int colg = colBase + 8 * s + 2 * q;        // < 304 by construction
            uint32_t wA = *(const uint32_t*)(smemc + SM_X + rowA * XROW + (colg & ~3));
            uint32_t wB = *(const uint32_t*)(smemc + SM_X + rowB * XROW + (colg & ~3));
            int sxA = ((int)(wA << (24 - 8 * lo))) >> 24;
            int syA = ((int)(wA << (16 - 8 * lo))) >> 24;
            int sxB = ((int)(wB << (24 - 8 * lo))) >> 24;
            int syB = ((int)(wB << (16 - 8 * lo))) >> 24;
            aA[t][0] = fmaf((float)sxA, (float)acc[t][s][0],
                       fmaf((float)syA, (float)acc[t][s][1], aA[t][0]));
            aA[t][1] = fmaf((float)sxB, (float)acc[t][s][2],
                       fmaf((float)syB, (float)acc[t][s][3], aA[t][1]));
            if (hasPrev && colg < Dn) {
                float2 pvA = __ldg((const float2*)(pA + colg));
                float2 pvB = __ldg((const float2*)(pB + colg));
                cA[t][0] = fmaf(pvA.x, (float)acc[t][s][0],
                           fmaf(pvA.y, (float)acc[t][s][1], cA[t][0]));
                cA[t][1] = fmaf(pvB.x, (float)acc[t][s][2],
                           fmaf(pvB.y, (float)acc[t][s][3], cA[t][1]));
            }
        }
    }
}

// ============ kernel 2: int8 MMA GEMM + fused score dots ============
__global__ __launch_bounds__(256, 2) void score_kernel(const float* __restrict__ S) {
    extern __shared__ __align__(16) char smem[];
    const uint32_t sb = smem_to_u32(smem);
    const int tid  = threadIdx.x;
    const int lane = tid & 31;
    const int wid  = tid >> 5;
    const int wm   = wid & 3;            // 32-row slice
    const int wn   = wid >> 2;           // n-slice within chunk
    const int r0   = 32 * wm;
    const int g    = lane >> 2, q = lane & 3;
    const int  tile = blockIdx.x;
    const size_t m0 = (size_t)tile * 128;
    const bool hasPrev = (tile >= 32);
    float* sAlpha = (float*)(smem + SM_AL);

    // ---- stage X: warp owns 16 rows; per row: amax -> per-row quantize -> int8 smem ----
    {
        const int rbase = wid * 16;
        const int nf = (lane < 11) ? 3 : 2;          // f4 indices lane, lane+32, lane+64
        float4 c0, c1, c2;
        {
            const float4* rp = (const float4*)(S + (m0 + rbase) * Dn);
            c0 = __ldg(rp + lane);
            c1 = __ldg(rp + lane + 32);
            c2 = (nf == 3) ? __ldg(rp + lane + 64) : make_float4(0.f, 0.f, 0.f, 0.f);
        }
        for (int rr = 0; rr < 16; rr++) {
            const int row = rbase + rr;
            float4 n0, n1, n2;
            if (rr < 15) {
                const float4* rp = (const float4*)(S + (m0 + row + 1) * Dn);
                n0 = __ldg(rp + lane);
                n1 = __ldg(rp + lane + 32);
                n2 = (nf == 3) ? __ldg(rp + lane + 64) : make_float4(0.f, 0.f, 0.f, 0.f);
            }
            float mx = fmaxf(fmaxf(fmaxf(fabsf(c0.x), fabsf(c0.y)), fmaxf(fabsf(c0.z), fabsf(c0.w))),
                       fmaxf(fmaxf(fabsf(c1.x), fabsf(c1.y)), fmaxf(fabsf(c1.z), fabsf(c1.w))));
            mx = fmaxf(mx, fmaxf(fmaxf(fabsf(c2.x), fabsf(c2.y)), fmaxf(fabsf(c2.z), fabsf(c2.w))));
            #pragma unroll
            for (int off = 16; off > 0; off >>= 1)
                mx = fmaxf(mx, __shfl_xor_sync(0xffffffffu, mx, off));
            const float inv = 127.0f / mx;
            char* rowp = smem + SM_X + row * XROW;
            #pragma unroll
            for (int j = 0; j < 3; j++) {
                if (j < nf) {
                    float4 v = (j == 0) ? c0 : (j == 1) ? c1 : c2;
                    uint32_t p = ((uint32_t)(__float2int_rn(v.x * inv) & 255))
                               | ((uint32_t)(__float2int_rn(v.y * inv) & 255) << 8)
                               | ((uint32_t)(__float2int_rn(v.z * inv) & 255) << 16)
                               | ((uint32_t)(__float2int_rn(v.w * inv) & 255) << 24);
                    *(uint32_t*)(rowp + 4 * (lane + 32 * j)) = p;
                }
            }
            if (lane >= 27) *(uint32_t*)(rowp + 4 * (75 + lane - 27)) = 0u;  // cols 300..319
            if (lane == 0) sAlpha[row] = mx * (1.0f / 127.0f);
            c0 = n0; c1 = n1; c2 = n2;
        }
    }
    __syncthreads();

    const uint32_t aBase0 = sb + SM_X + (r0 + (lane & 15)) * XROW + (lane >> 4) * 16;
    const uint32_t aBase1 = aBase0 + 16 * XROW;

    float aA[2][2] = {{0.f,0.f},{0.f,0.f}};
    float cA[2][2] = {{0.f,0.f},{0.f,0.f}};

    // chunk 0: 160 cols (10 s-tiles), chunk 1: 144 cols (9 s-tiles)
    {
        const uint32_t* bp0 = g_Wfrag + ((size_t)(0 * 20 + wn) * 32 + lane) * 20;
        run_chunk<10>((const char*)smem, aBase0, aBase1, bp0, 80 * wn,
                      S, m0, hasPrev, r0, g, q, aA, cA);
    }
    {
        const uint32_t* bp1 = g_Wfrag + ((size_t)(1 * 20 + wn) * 32 + lane) * 20;
        run_chunk<9>((const char*)smem, aBase0, aBase1, bp1, 160 + 72 * wn,
                     S, m0, hasPrev, r0, g, q, aA, cA);
    }

    // ---- final reduce: q lanes, then the 2 n-warps via smem; apply scales ----
    float* sRA = (float*)(smem + SM_RA);
    float* sRC = (float*)(smem + SM_RC);
    #pragma unroll
    for (int t = 0; t < 2; t++)
        #pragma unroll
        for (int h = 0; h < 2; h++) {
            float a = aA[t][h], c = cA[t][h];
            a += __shfl_xor_sync(0xffffffffu, a, 1);
            a += __shfl_xor_sync(0xffffffffu, a, 2);
            c += __shfl_xor_sync(0xffffffffu, c, 1);
            c += __shfl_xor_sync(0xffffffffu, c, 2);
            if (q == 0) {
                int row = r0 + 16 * t + 8 * h + g;
                sRA[wn * 128 + row] = a;
                sRC[wn * 128 + row] = c;
            }
        }
    __syncthreads();
    if (tid < 128) {
        const float beta = __uint_as_float(g_amaxBits) * (1.0f / 127.0f);
        const float al   = sAlpha[tid];
        g_A[m0 + tid] = 0.5f * al * al * beta * (sRA[tid] + sRA[128 + tid]);
        if (hasPrev)
            g_C[m0 + tid] = 0.5f * al * beta * (sRC[tid] + sRC[128 + tid]);
    }
}

// ============ kernel 3: l-streaming blend (R13 version, untouched) ============
__global__ __launch_bounds__(256) void blend_kernel(const float* __restrict__ S,
                                                    const int* __restrict__ sizes,
                                                    float* __restrict__ out) {
    const int warp = threadIdx.x >> 5;
    const int lane = threadIdx.x & 31;
    const int b    = blockIdx.x * 8 + warp;
    const int sz   = sizes[b];
    const float inv_d = 1.0f / 300.0f;

    bool val[3];
    #pragma unroll
    for (int j = 0; j < 3; j++) val[j] = (j * 32 + lane) < 75;

    const size_t slabF4 = (size_t)Bn * Dn / 4;        // 307200
    const float4* rp = (const float4*)(S + (size_t)b * Dn);
    float4*       op = (float4*)(out + (size_t)b * Dn);

    const float4 z = make_float4(0.f, 0.f, 0.f, 0.f);
    float4 prv[3] = {z, z, z}, cur[3], nxt[3];
    #pragma unroll
    for (int j = 0; j < 3; j++) cur[j] = val[j] ? __ldg(rp + j * 32 + lane) : z;

    for (int l = 0; l < Ln; ++l) {
        const bool hasN = (l < Ln - 1);
        #pragma unroll
        for (int j = 0; j < 3; j++)
            nxt[j] = (hasN && val[j]) ? __ldg(rp + slabF4 + j * 32 + lane) : z;

        float l1 = g_A[l * Bn + b] * inv_d;
        float l0 = (l >= 1 && l < sz)     ? g_C[l * Bn + b] * inv_d       : -INFINITY;
        float l2 = (hasN && l < sz - 1)   ? g_C[(l + 1) * Bn + b] * inv_d : -INFINITY;

        float mx = fmaxf(l1, fmaxf(l0, l2));
        float e0 = expf(l0 - mx), e1 = expf(l1 - mx), e2 = expf(l2 - mx);
        float inv = 1.0f / (e0 + e1 + e2);
        float w0 = e0 * inv, w1 = e1 * inv, w2 = e2 * inv;

        #pragma unroll
        for (int j = 0; j < 3; j++) {
            if (val[j]) {
                float4 r;
                r.x = w1 * cur[j].x + w0 * prv[j].x + w2 * nxt[j].x;
                r.y = w1 * cur[j].y + w0 * prv[j].y + w2 * nxt[j].y;
                r.z = w1 * cur[j].z + w0 * prv[j].z + w2 * nxt[j].z;
                r.w = w1 * cur[j].w + w0 * prv[j].w + w2 * nxt[j].w;
                op[j * 32 + lane] = r;
            }
        }
        #pragma unroll
        for (int j = 0; j < 3; j++) { prv[j] = cur[j]; cur[j] = nxt[j]; }
        rp += slabF4;
        op += slabF4;
    }
}

// ==================== launch ====================
extern "C" void kernel_launch(void* const* d_in, const int* in_sizes, int n_in,
                              void* d_out, int out_size) {
    const float* S     = (const float*)d_in[0];
    const int*   sizes = (const int*)d_in[1];
    const float* W     = (const float*)d_in[2];
    float*       out   = (float*)d_out;
    (void)in_sizes; (void)n_in; (void)out_size;

    zeroAmax_kernel<<<1, 1>>>();
    amax_kernel<<<(Dn * Dn + 255) / 256, 256>>>(W);
    prepW_kernel<<<(NBLOB * 32 * 20 + 255) / 256, 256>>>(W);

    cudaFuncSetAttribute(score_kernel, cudaFuncAttributeMaxDynamicSharedMemorySize, DYN_SMEM);
    score_kernel<<<4096, 256, DYN_SMEM>>>(S);

    blend_kernel<<<Bn / 8, 256>>>(S, sizes, out);
}

// round 15
// speedup vs baseline: 1.5038x; 1.5038x over previous
#include <cuda_runtime.h>
#include <cuda_bf16.h>
#include <math.h>
#include <stdint.h>

#define Ln 128
#define Bn 4096
#define Dn 300
#define XROW 624                // 304 bf16 + 16B pad
#define SM_X  0
#define SM_RA 79872             // 128*624
#define SM_RC 80896
#define DYN_SMEM 81920

// Fragment-ordered B image: blob (ch,ks,wn) of [lane][20 u32] (ch1 uses 18 + 2 pad).
// blob index = ch*38 + ks*2 + wn; per-ks stride = 2 blobs = 1280 u32.
// ch0: n = wn*80 + 8s + g (s<10); ch1: n = 160 + wn*72 + 8s + g (s<9). k0 = ks*16 + half*8 + 2q.
#define NBLOB (2*19*2)
__device__ __align__(16) uint32_t g_Wfrag[NBLOB * 32 * 20];
__device__ float g_A[Ln * Bn];
__device__ float g_C[Ln * Bn];

__device__ __forceinline__ uint32_t smem_to_u32(const void* p) {
    uint32_t a;
    asm("{ .reg .u64 t; cvta.to.shared.u64 t, %1; cvt.u32.u64 %0, t; }" : "=r"(a) : "l"(p));
    return a;
}

#define LDSM_X4(r, addr)                                                        \
    asm volatile("ldmatrix.sync.aligned.m8n8.x4.shared.b16 {%0,%1,%2,%3}, [%4];"\
        : "=r"((r)[0]),"=r"((r)[1]),"=r"((r)[2]),"=r"((r)[3]) : "r"(addr))
#define MMA16816(d, a, b0, b1)                                                  \
    asm volatile("mma.sync.aligned.m16n8k16.row.col.f32.bf16.bf16.f32 "         \
        "{%0,%1,%2,%3}, {%4,%5,%6,%7}, {%8,%9}, {%0,%1,%2,%3};"                 \
        : "+f"((d)[0]),"+f"((d)[1]),"+f"((d)[2]),"+f"((d)[3])                   \
        : "r"((a)[0]),"r"((a)[1]),"r"((a)[2]),"r"((a)[3]), "r"(b0),"r"(b1))

// streaming float4 load / store (evict-first; no reuse data)
__device__ __forceinline__ float4 ldcs_f4(const float4* p) {
    float4 v;
    asm volatile("ld.global.cs.v4.f32 {%0,%1,%2,%3}, [%4];"
                 : "=f"(v.x), "=f"(v.y), "=f"(v.z), "=f"(v.w) : "l"(p));
    return v;
}
__device__ __forceinline__ void stcs_f4(float4* p, float4 v) {
    asm volatile("st.global.cs.v4.f32 [%0], {%1,%2,%3,%4};"
                 :: "l"(p), "f"(v.x), "f"(v.y), "f"(v.z), "f"(v.w) : "memory");
}

// ============ kernel 1: build fragment-ordered bf16 Ws image ============
__global__ void prepW_kernel(const float* __restrict__ W) {
    int idx = blockIdx.x * 256 + threadIdx.x;
    if (idx >= NBLOB * 32 * 20) return;
    int su   = idx % 20;
    int lane = (idx / 20) & 31;
    int blob = idx / (32 * 20);
    int wn = blob & 1, ks = (blob >> 1) % 19, ch = blob / 38;
    int g = lane >> 2, q = lane & 3;
    uint32_t pk = 0u;
    const int nsu = ch ? 18 : 20;        // valid u32 per lane: ch1 has 9 s-tiles
    if (su < nsu) {
        int s = su >> 1, half = su & 1;
        int n  = ch ? (160 + wn * 72 + 8 * s + g) : (wn * 80 + 8 * s + g);
        int k0 = ks * 16 + half * 8 + 2 * q;
        float v0 = 0.f, v1 = 0.f;
        if (n < Dn) {
            if (k0 < Dn)     v0 = W[k0 * Dn + n] + W[n * Dn + k0];
            if (k0 + 1 < Dn) v1 = W[(k0 + 1) * Dn + n] + W[n * Dn + k0 + 1];
        }
        __nv_bfloat162 p = __floats2bfloat162_rn(v0, v1);
        pk = *(uint32_t*)&p;
    }
    g_Wfrag[idx] = pk;
}

// ---------------- templated chunk body (k-loop + dot epilogue) ----------------
template <int NS>
__device__ __forceinline__ void run_chunk(
    const char* smemc, uint32_t aBase0, uint32_t aBase1,
    const uint32_t* bp, int colBase,
    const float* __restrict__ S, size_t m0, bool hasPrev,
    int r0, int g, int q, float (&aA)[2][2], float (&cA)[2][2])
{
    float acc[2][NS][4];
    #pragma unroll
    for (int t = 0; t < 2; t++)
        #pragma unroll
        for (int s = 0; s < NS; s++)
            #pragma unroll
            for (int i = 0; i < 4; i++) acc[t][s][i] = 0.f;

    #pragma unroll 1
    for (int ks = 0; ks < 19; ks++) {
        uint32_t a0[4], a1[4];
        LDSM_X4(a0, aBase0 + ks * 32);
        LDSM_X4(a1, aBase1 + ks * 32);
        uint32_t bw[2 * NS];
        #pragma unroll
        for (int j = 0; j < NS / 2; j++) {
            uint4 v = __ldg((const uint4*)bp + j);
            bw[4 * j] = v.x; bw[4 * j + 1] = v.y; bw[4 * j + 2] = v.z; bw[4 * j + 3] = v.w;
        }
        if constexpr (NS & 1) {
            uint2 v = __ldg((const uint2*)(bp + 4 * (NS / 2)));
            bw[2 * NS - 2] = v.x; bw[2 * NS - 1] = v.y;
        }
        bp += 2 * 32 * 20;               // next ks (stride 5120B)
        #pragma unroll
        for (int s = 0; s < NS; s++) {
            MMA16816(acc[0][s], a0, bw[2 * s], bw[2 * s + 1]);
            MMA16816(acc[1][s], a1, bw[2 * s], bw[2 * s + 1]);
        }
    }

    // dot epilogue: self from X smem, prev from gmem (L2-hot)
    #pragma unroll
    for (int t = 0; t < 2; t++) {
        const int rowA = r0 + 16 * t + g;
        const int rowB = rowA + 8;
        const float* pA = S + (m0 + rowA - (size_t)Bn) * Dn;
        const float* pB = S + (m0 + rowB - (size_t)Bn) * Dn;
        #pragma unroll
        for (int s = 0; s < NS; s++) {
            const int colg = colBase + 8 * s + 2 * q;   // always < 304
            uint32_t svA = *(const uint32_t*)(smemc + SM_X + rowA * XROW + colg * 2);
            uint32_t svB = *(const uint32_t*)(smemc + SM_X + rowB * XROW + colg * 2);
            __nv_bfloat162 sA2 = *(__nv_bfloat162*)&svA;
            __nv_bfloat162 sB2 = *(__nv_bfloat162*)&svB;
            aA[t][0] = fmaf(__bfloat162float(sA2.x), acc[t][s][0],
                       fmaf(__bfloat162float(sA2.y), acc[t][s][1], aA[t][0]));
            aA[t][1] = fmaf(__bfloat162float(sB2.x), acc[t][s][2],
                       fmaf(__bfloat162float(sB2.y), acc[t][s][3], aA[t][1]));
            if (hasPrev && colg < Dn) {
                float2 pvA = __ldg((const float2*)(pA + colg));
                float2 pvB = __ldg((const float2*)(pB + colg));
                cA[t][0] = fmaf(pvA.x, acc[t][s][0], fmaf(pvA.y, acc[t][s][1], cA[t][0]));
                cA[t][1] = fmaf(pvB.x, acc[t][s][2], fmaf(pvB.y, acc[t][s][3], cA[t][1]));
            }
        }
    }
}

// ============ kernel 2: HMMA GEMM (B fragments from L2) + fused score dots ============
__global__ __launch_bounds__(256, 2) void score_kernel(const float* __restrict__ S) {
    extern __shared__ __align__(16) char smem[];
    const uint32_t sb = smem_to_u32(smem);
    const int tid  = threadIdx.x;
    const int lane = tid & 31;
    const int wid  = tid >> 5;
    const int wm   = wid & 3;            // 32-row slice
    const int wn   = wid >> 2;           // n-slice within chunk
    const int r0   = 32 * wm;
    const int g    = lane >> 2, q = lane & 3;
    const int  tile = blockIdx.x;
    const size_t m0 = (size_t)tile * 128;
    const bool hasPrev = (tile >= 32);

    // ---- stage X tile: 128 rows x 300 fp32 -> bf16 (cols 300..311 zero) ----
    const float* Sl = S + m0 * Dn;
    for (int idx = tid; idx < 128 * 75; idx += 256) {
        int r = idx / 75, f = idx % 75;
        float4 v = __ldg((const float4*)(Sl + (size_t)r * Dn) + f);
        __nv_bfloat162 p0 = __floats2bfloat162_rn(v.x, v.y);
        __nv_bfloat162 p1 = __floats2bfloat162_rn(v.z, v.w);
        *(uint2*)(smem + SM_X + r * XROW + f * 8) =
            make_uint2(*(uint32_t*)&p0, *(uint32_t*)&p1);
    }
    for (int idx = tid; idx < 128 * 3; idx += 256) {
        int r = idx / 3, w = idx % 3;
        *(uint2*)(smem + SM_X + r * XROW + 600 + w * 8) = make_uint2(0u, 0u);
    }
    __syncthreads();

    const uint32_t aBase0 = sb + SM_X + (r0 + (lane & 15)) * XROW + (lane >> 4) * 16;
    const uint32_t aBase1 = aBase0 + 16 * XROW;

    float aA[2][2] = {{0.f,0.f},{0.f,0.f}};
    float cA[2][2] = {{0.f,0.f},{0.f,0.f}};

    // chunk 0: 160 cols (10 s-tiles), chunk 1: 144 cols (9 s-tiles)
    {
        const uint32_t* bp0 = g_Wfrag + ((size_t)(0 * 38 + wn) * 32 + lane) * 20;
        run_chunk<10>((const char*)smem, aBase0, aBase1, bp0, 80 * wn,
                      S, m0, hasPrev, r0, g, q, aA, cA);
    }
    {
        const uint32_t* bp1 = g_Wfrag + ((size_t)(1 * 38 + wn) * 32 + lane) * 20;
        run_chunk<9>((const char*)smem, aBase0, aBase1, bp1, 160 + 72 * wn,
                     S, m0, hasPrev, r0, g, q, aA, cA);
    }

    // ---- final reduce: q lanes, then the 2 n-warps via smem ----
    float* sRA = (float*)(smem + SM_RA);
    float* sRC = (float*)(smem + SM_RC);
    #pragma unroll
    for (int t = 0; t < 2; t++)
        #pragma unroll
        for (int h = 0; h < 2; h++) {
            float a = aA[t][h], c = cA[t][h];
            a += __shfl_xor_sync(0xffffffffu, a, 1);
            a += __shfl_xor_sync(0xffffffffu, a, 2);
            c += __shfl_xor_sync(0xffffffffu, c, 1);
            c += __shfl_xor_sync(0xffffffffu, c, 2);
            if (q == 0) {
                int row = r0 + 16 * t + 8 * h + g;
                sRA[wn * 128 + row] = a;
                sRC[wn * 128 + row] = c;
            }
        }
    __syncthreads();
    if (tid < 128) {
        g_A[m0 + tid] = 0.5f * (sRA[tid] + sRA[128 + tid]);
        if (hasPrev) g_C[m0 + tid] = 0.5f * (sRC[tid] + sRC[128 + tid]);
    }
}

// ============ kernel 3: l-streaming blend (streaming cache hints) ============
__global__ __launch_bounds__(256) void blend_kernel(const float* __restrict__ S,
                                                    const int* __restrict__ sizes,
                                                    float* __restrict__ out) {
    const int warp = threadIdx.x >> 5;
    const int lane = threadIdx.x & 31;
    const int b    = blockIdx.x * 8 + warp;
    const int sz   = sizes[b];
    const float inv_d = 1.0f / 300.0f;

    bool val[3];
    #pragma unroll
    for (int j = 0; j < 3; j++) val[j] = (j * 32 + lane) < 75;

    const size_t slabF4 = (size_t)Bn * Dn / 4;        // 307200
    const float4* rp = (const float4*)(S + (size_t)b * Dn);
    float4*       op = (float4*)(out + (size_t)b * Dn);

    const float4 z = make_float4(0.f, 0.f, 0.f, 0.f);
    float4 prv[3] = {z, z, z}, cur[3], nxt[3];
    #pragma unroll
    for (int j = 0; j < 3; j++) cur[j] = val[j] ? ldcs_f4(rp + j * 32 + lane) : z;

    for (int l = 0; l < Ln; ++l) {
        const bool hasN = (l < Ln - 1);
        #pragma unroll
        for (int j = 0; j < 3; j++)
            nxt[j] = (hasN && val[j]) ? ldcs_f4(rp + slabF4 + j * 32 + lane) : z;

        float l1 = g_A[l * Bn + b] * inv_d;
        float l0 = (l >= 1 && l < sz)     ? g_C[l * Bn + b] * inv_d       : -INFINITY;
        float l2 = (hasN && l < sz - 1)   ? g_C[(l + 1) * Bn + b] * inv_d : -INFINITY;

        float mx = fmaxf(l1, fmaxf(l0, l2));
        float e0 = expf(l0 - mx), e1 = expf(l1 - mx), e2 = expf(l2 - mx);
        float inv = 1.0f / (e0 + e1 + e2);
        float w0 = e0 * inv, w1 = e1 * inv, w2 = e2 * inv;

        #pragma unroll
        for (int j = 0; j < 3; j++) {
            if (val[j]) {
                float4 r;
                r.x = w1 * cur[j].x + w0 * prv[j].x + w2 * nxt[j].x;
                r.y = w1 * cur[j].y + w0 * prv[j].y + w2 * nxt[j].y;
                r.z = w1 * cur[j].z + w0 * prv[j].z + w2 * nxt[j].z;
                r.w = w1 * cur[j].w + w0 * prv[j].w + w2 * nxt[j].w;
                stcs_f4(op + j * 32 + lane, r);
            }
        }
        #pragma unroll
        for (int j = 0; j < 3; j++) { prv[j] = cur[j]; cur[j] = nxt[j]; }
        rp += slabF4;
        op += slabF4;
    }
}

// ==================== launch ====================
extern "C" void kernel_launch(void* const* d_in, const int* in_sizes, int n_in,
                              void* d_out, int out_size) {
    const float* S     = (const float*)d_in[0];
    const int*   sizes = (const int*)d_in[1];
    const float* W     = (const float*)d_in[2];
    float*       out   = (float*)d_out;
    (void)in_sizes; (void)n_in; (void)out_size;

    prepW_kernel<<<(NBLOB * 32 * 20 + 255) / 256, 256>>>(W);

    cudaFuncSetAttribute(score_kernel, cudaFuncAttributeMaxDynamicSharedMemorySize, DYN_SMEM);
    score_kernel<<<4096, 256, DYN_SMEM>>>(S);

    blend_kernel<<<Bn / 8, 256>>>(S, sizes, out);
}

// round 16
// speedup vs baseline: 1.5367x; 1.0218x over previous
#include <cuda_runtime.h>
#include <cuda_bf16.h>
#include <math.h>
#include <stdint.h>

#define Ln 128
#define Bn 4096
#define Dn 300
#define XROW 624                // 304 bf16 + 16B pad
#define SM_X  0
#define SM_RA 79872             // 128*624
#define SM_RC 80896
#define DYN_SMEM 81920

// Fragment-ordered B image: blob (ch,ks,wn) of [lane][20 u32] (ch1 uses 18 + 2 pad).
// blob index = ch*38 + ks*2 + wn; per-ks stride = 2 blobs = 1280 u32.
// ch0: n = wn*80 + 8s + g (s<10); ch1: n = 160 + wn*72 + 8s + g (s<9). k0 = ks*16 + half*8 + 2q.
#define NBLOB (2*19*2)
__device__ __align__(16) uint32_t g_Wfrag[NBLOB * 32 * 20];
__device__ float g_A[Ln * Bn];
__device__ float g_C[Ln * Bn];

__device__ __forceinline__ uint32_t smem_to_u32(const void* p) {
    uint32_t a;
    asm("{ .reg .u64 t; cvta.to.shared.u64 t, %1; cvt.u32.u64 %0, t; }" : "=r"(a) : "l"(p));
    return a;
}

#define LDSM_X4(r, addr)                                                        \
    asm volatile("ldmatrix.sync.aligned.m8n8.x4.shared.b16 {%0,%1,%2,%3}, [%4];"\
        : "=r"((r)[0]),"=r"((r)[1]),"=r"((r)[2]),"=r"((r)[3]) : "r"(addr))
#define MMA16816(d, a, b0, b1)                                                  \
    asm volatile("mma.sync.aligned.m16n8k16.row.col.f32.bf16.bf16.f32 "         \
        "{%0,%1,%2,%3}, {%4,%5,%6,%7}, {%8,%9}, {%0,%1,%2,%3};"                 \
        : "+f"((d)[0]),"+f"((d)[1]),"+f"((d)[2]),"+f"((d)[3])                   \
        : "r"((a)[0]),"r"((a)[1]),"r"((a)[2]),"r"((a)[3]), "r"(b0),"r"(b1))

// ============ kernel 1: build fragment-ordered bf16 Ws image ============
__global__ void prepW_kernel(const float* __restrict__ W) {
    int idx = blockIdx.x * 256 + threadIdx.x;
    if (idx >= NBLOB * 32 * 20) return;
    int su   = idx % 20;
    int lane = (idx / 20) & 31;
    int blob = idx / (32 * 20);
    int wn = blob & 1, ks = (blob >> 1) % 19, ch = blob / 38;
    int g = lane >> 2, q = lane & 3;
    uint32_t pk = 0u;
    const int nsu = ch ? 18 : 20;        // valid u32 per lane: ch1 has 9 s-tiles
    if (su < nsu) {
        int s = su >> 1, half = su & 1;
        int n  = ch ? (160 + wn * 72 + 8 * s + g) : (wn * 80 + 8 * s + g);
        int k0 = ks * 16 + half * 8 + 2 * q;
        float v0 = 0.f, v1 = 0.f;
        if (n < Dn) {
            if (k0 < Dn)     v0 = W[k0 * Dn + n] + W[n * Dn + k0];
            if (k0 + 1 < Dn) v1 = W[(k0 + 1) * Dn + n] + W[n * Dn + k0 + 1];
        }
        __nv_bfloat162 p = __floats2bfloat162_rn(v0, v1);
        pk = *(uint32_t*)&p;
    }
    g_Wfrag[idx] = pk;
}

// ---------------- templated chunk body (k-loop + dot epilogue) ----------------
template <int NS>
__device__ __forceinline__ void run_chunk(
    const char* smemc, uint32_t aBase0, uint32_t aBase1,
    const uint32_t* bp, int colBase,
    const float* __restrict__ S, size_t m0, bool hasPrev,
    int r0, int g, int q, float (&aA)[2][2], float (&cA)[2][2])
{
    float acc[2][NS][4];
    #pragma unroll
    for (int t = 0; t < 2; t++)
        #pragma unroll
        for (int s = 0; s < NS; s++)
            #pragma unroll
            for (int i = 0; i < 4; i++) acc[t][s][i] = 0.f;

    #pragma unroll 1
    for (int ks = 0; ks < 19; ks++) {
        uint32_t a0[4], a1[4];
        LDSM_X4(a0, aBase0 + ks * 32);
        LDSM_X4(a1, aBase1 + ks * 32);
        uint32_t bw[2 * NS];
        #pragma unroll
        for (int j = 0; j < NS / 2; j++) {
            uint4 v = __ldg((const uint4*)bp + j);
            bw[4 * j] = v.x; bw[4 * j + 1] = v.y; bw[4 * j + 2] = v.z; bw[4 * j + 3] = v.w;
        }
        if constexpr (NS & 1) {
            uint2 v = __ldg((const uint2*)(bp + 4 * (NS / 2)));
            bw[2 * NS - 2] = v.x; bw[2 * NS - 1] = v.y;
        }
        bp += 2 * 32 * 20;               // next ks (stride 5120B)
        #pragma unroll
        for (int s = 0; s < NS; s++) {
            MMA16816(acc[0][s], a0, bw[2 * s], bw[2 * s + 1]);
            MMA16816(acc[1][s], a1, bw[2 * s], bw[2 * s + 1]);
        }
    }

    // dot epilogue: self from X smem, prev from gmem (L2-hot)
    #pragma unroll
    for (int t = 0; t < 2; t++) {
        const int rowA = r0 + 16 * t + g;
        const int rowB = rowA + 8;
        const float* pA = S + (m0 + rowA - (size_t)Bn) * Dn;
        const float* pB = S + (m0 + rowB - (size_t)Bn) * Dn;
        #pragma unroll
        for (int s = 0; s < NS; s++) {
            const int colg = colBase + 8 * s + 2 * q;   // always < 304
            uint32_t svA = *(const uint32_t*)(smemc + SM_X + rowA * XROW + colg * 2);
            uint32_t svB = *(const uint32_t*)(smemc + SM_X + rowB * XROW + colg * 2);
            __nv_bfloat162 sA2 = *(__nv_bfloat162*)&svA;
            __nv_bfloat162 sB2 = *(__nv_bfloat162*)&svB;
            aA[t][0] = fmaf(__bfloat162float(sA2.x), acc[t][s][0],
                       fmaf(__bfloat162float(sA2.y), acc[t][s][1], aA[t][0]));
            aA[t][1] = fmaf(__bfloat162float(sB2.x), acc[t][s][2],
                       fmaf(__bfloat162float(sB2.y), acc[t][s][3], aA[t][1]));
            if (hasPrev && colg < Dn) {
                float2 pvA = __ldg((const float2*)(pA + colg));
                float2 pvB = __ldg((const float2*)(pB + colg));
                cA[t][0] = fmaf(pvA.x, acc[t][s][0], fmaf(pvA.y, acc[t][s][1], cA[t][0]));
                cA[t][1] = fmaf(pvB.x, acc[t][s][2], fmaf(pvB.y, acc[t][s][3], cA[t][1]));
            }
        }
    }
}

// ============ kernel 2: HMMA GEMM (B fragments from L2) + fused score dots ============
__global__ __launch_bounds__(256, 2) void score_kernel(const float* __restrict__ S) {
    extern __shared__ __align__(16) char smem[];
    const uint32_t sb = smem_to_u32(smem);
    const int tid  = threadIdx.x;
    const int lane = tid & 31;
    const int wid  = tid >> 5;
    const int wm   = wid & 3;            // 32-row slice
    const int wn   = wid >> 2;           // n-slice within chunk
    const int r0   = 32 * wm;
    const int g    = lane >> 2, q = lane & 3;
    const int  tile = blockIdx.x;
    const size_t m0 = (size_t)tile * 128;
    const bool hasPrev = (tile >= 32);

    // ---- stage X tile: 128 rows x 300 fp32 -> bf16 (cols 300..311 zero) ----
    const float* Sl = S + m0 * Dn;
    for (int idx = tid; idx < 128 * 75; idx += 256) {
        int r = idx / 75, f = idx % 75;
        float4 v = __ldg((const float4*)(Sl + (size_t)r * Dn) + f);
        __nv_bfloat162 p0 = __floats2bfloat162_rn(v.x, v.y);
        __nv_bfloat162 p1 = __floats2bfloat162_rn(v.z, v.w);
        *(uint2*)(smem + SM_X + r * XROW + f * 8) =
            make_uint2(*(uint32_t*)&p0, *(uint32_t*)&p1);
    }
    for (int idx = tid; idx < 128 * 3; idx += 256) {
        int r = idx / 3, w = idx % 3;
        *(uint2*)(smem + SM_X + r * XROW + 600 + w * 8) = make_uint2(0u, 0u);
    }
    __syncthreads();

    const uint32_t aBase0 = sb + SM_X + (r0 + (lane & 15)) * XROW + (lane >> 4) * 16;
    const uint32_t aBase1 = aBase0 + 16 * XROW;

    float aA[2][2] = {{0.f,0.f},{0.f,0.f}};
    float cA[2][2] = {{0.f,0.f},{0.f,0.f}};

    // chunk 0: 160 cols (10 s-tiles), chunk 1: 144 cols (9 s-tiles)
    {
        const uint32_t* bp0 = g_Wfrag + ((size_t)(0 * 38 + wn) * 32 + lane) * 20;
        run_chunk<10>((const char*)smem, aBase0, aBase1, bp0, 80 * wn,
                      S, m0, hasPrev, r0, g, q, aA, cA);
    }
    {
        const uint32_t* bp1 = g_Wfrag + ((size_t)(1 * 38 + wn) * 32 + lane) * 20;
        run_chunk<9>((const char*)smem, aBase0, aBase1, bp1, 160 + 72 * wn,
                     S, m0, hasPrev, r0, g, q, aA, cA);
    }

    // ---- final reduce: q lanes, then the 2 n-warps via smem ----
    float* sRA = (float*)(smem + SM_RA);
    float* sRC = (float*)(smem + SM_RC);
    #pragma unroll
    for (int t = 0; t < 2; t++)
        #pragma unroll
        for (int h = 0; h < 2; h++) {
            float a = aA[t][h], c = cA[t][h];
            a += __shfl_xor_sync(0xffffffffu, a, 1);
            a += __shfl_xor_sync(0xffffffffu, a, 2);
            c += __shfl_xor_sync(0xffffffffu, c, 1);
            c += __shfl_xor_sync(0xffffffffu, c, 2);
            if (q == 0) {
                int row = r0 + 16 * t + 8 * h + g;
                sRA[wn * 128 + row] = a;
                sRC[wn * 128 + row] = c;
            }
        }
    __syncthreads();
    if (tid < 128) {
        g_A[m0 + tid] = 0.5f * (sRA[tid] + sRA[128 + tid]);
        if (hasPrev) g_C[m0 + tid] = 0.5f * (sRC[tid] + sRC[128 + tid]);
    }
}

// ============ kernel 3: l-streaming blend (R13 warp code; 128-thr CTAs) ============
__global__ __launch_bounds__(128) void blend_kernel(const float* __restrict__ S,
                                                    const int* __restrict__ sizes,
                                                    float* __restrict__ out) {
    const int warp = threadIdx.x >> 5;
    const int lane = threadIdx.x & 31;
    const int b    = blockIdx.x * 4 + warp;
    const int sz   = sizes[b];
    const float inv_d = 1.0f / 300.0f;

    bool val[3];
    #pragma unroll
    for (int j = 0; j < 3; j++) val[j] = (j * 32 + lane) < 75;

    const size_t slabF4 = (size_t)Bn * Dn / 4;        // 307200
    const float4* rp = (const float4*)(S + (size_t)b * Dn);
    float4*       op = (float4*)(out + (size_t)b * Dn);

    const float4 z = make_float4(0.f, 0.f, 0.f, 0.f);
    float4 prv[3] = {z, z, z}, cur[3], nxt[3];
    #pragma unroll
    for (int j = 0; j < 3; j++) cur[j] = val[j] ? __ldg(rp + j * 32 + lane) : z;

    for (int l = 0; l < Ln; ++l) {
        const bool hasN = (l < Ln - 1);
        #pragma unroll
        for (int j = 0; j < 3; j++)
            nxt[j] = (hasN && val[j]) ? __ldg(rp + slabF4 + j * 32 + lane) : z;

        float l1 = g_A[l * Bn + b] * inv_d;
        float l0 = (l >= 1 && l < sz)     ? g_C[l * Bn + b] * inv_d       : -INFINITY;
        float l2 = (hasN && l < sz - 1)   ? g_C[(l + 1) * Bn + b] * inv_d : -INFINITY;

        float mx = fmaxf(l1, fmaxf(l0, l2));
        float e0 = expf(l0 - mx), e1 = expf(l1 - mx), e2 = expf(l2 - mx);
        float inv = 1.0f / (e0 + e1 + e2);
        float w0 = e0 * inv, w1 = e1 * inv, w2 = e2 * inv;

        #pragma unroll
        for (int j = 0; j < 3; j++) {
            if (val[j]) {
                float4 r;
                r.x = w1 * cur[j].x + w0 * prv[j].x + w2 * nxt[j].x;
                r.y = w1 * cur[j].y + w0 * prv[j].y + w2 * nxt[j].y;
                r.z = w1 * cur[j].z + w0 * prv[j].z + w2 * nxt[j].z;
                r.w = w1 * cur[j].w + w0 * prv[j].w + w2 * nxt[j].w;
                op[j * 32 + lane] = r;
            }
        }
        #pragma unroll
        for (int j = 0; j < 3; j++) { prv[j] = cur[j]; cur[j] = nxt[j]; }
        rp += slabF4;
        op += slabF4;
    }
}

// ==================== launch ====================
extern "C" void kernel_launch(void* const* d_in, const int* in_sizes, int n_in,
                              void* d_out, int out_size) {
    const float* S     = (const float*)d_in[0];
    const int*   sizes = (const int*)d_in[1];
    const float* W     = (const float*)d_in[2];
    float*       out   = (float*)d_out;
    (void)in_sizes; (void)n_in; (void)out_size;

    prepW_kernel<<<(NBLOB * 32 * 20 + 255) / 256, 256>>>(W);

    cudaFuncSetAttribute(score_kernel, cudaFuncAttributeMaxDynamicSharedMemorySize, DYN_SMEM);
    score_kernel<<<4096, 256, DYN_SMEM>>>(S);

    blend_kernel<<<Bn / 4, 128>>>(S, sizes, out);
}